// round 2
// baseline (speedup 1.0000x reference)
#include <cuda_runtime.h>
#include <cstdint>

// y_i = || x_i * tril(L) ||^2 + b.x_i + c
// z = x @ tril(L) via m16n8k8 TF32 mma.sync; y accumulated from fragments in
// registers (z never hits memory). Persistent CTAs: tril(L)^T built once per
// CTA in swizzled smem. b.x computed from pre-tf32 fp32 A values (exact path).

__global__ __launch_bounds__(256, 2)
void psd_quad_tf32_kernel(const float* __restrict__ x,
                          const float* __restrict__ Lm,
                          const float* __restrict__ bv,
                          const float* __restrict__ cv,
                          float* __restrict__ out,
                          int ntiles)
{
    extern __shared__ float smem[];
    float* Bs = smem;            // 128x128: Bs[n][k] = tril(L)[k][n], tf32-rounded,
                                 // stored at column (k ^ ((n&7)<<2)) for bank-conflict-free frags
    float* bs = smem + 128 * 128;

    const int tid = threadIdx.x;

    // Build B (tril + tf32 round + swizzle). Coalesced LDG over n (fast dim).
    for (int idx = tid; idx < 128 * 128; idx += 256) {
        int n = idx & 127;
        int k = idx >> 7;
        float v = (k >= n) ? Lm[k * 128 + n] : 0.0f;
        uint32_t vt;
        asm("cvt.rna.tf32.f32 %0, %1;" : "=r"(vt) : "f"(v));
        Bs[n * 128 + (k ^ ((n & 7) << 2))] = __uint_as_float(vt);
    }
    if (tid < 128) bs[tid] = bv[tid];
    __syncthreads();

    const float cval = cv[0];

    const int warp = tid >> 5;
    const int lane = tid & 31;
    const int q = lane >> 2;   // group id (row within m-tile)
    const int a = lane & 3;    // thread-in-group (k within frag)
    const int qs = q << 2;     // swizzle term

    // Each warp owns a 16-row m-tile; CTA = 8 warps = 128 rows per tile.
    for (int tile = blockIdx.x; tile < ntiles; tile += gridDim.x) {
        const int row0 = tile * 128 + warp * 16 + q;
        const float* x0 = x + (size_t)row0 * 128;
        const float* x1 = x0 + 8 * 128;

        float acc[16][4];
#pragma unroll
        for (int nt = 0; nt < 16; nt++) {
            acc[nt][0] = 0.f; acc[nt][1] = 0.f; acc[nt][2] = 0.f; acc[nt][3] = 0.f;
        }
        float bd0 = 0.f, bd1 = 0.f;

#pragma unroll 2
        for (int kt = 0; kt < 16; kt++) {
            const int k0 = kt * 8 + a;
            // A fragment (m16n8k8 row-major): a0=[q][a] a1=[q+8][a] a2=[q][a+4] a3=[q+8][a+4]
            float a0 = x0[k0];
            float a2 = x0[k0 + 4];
            float a1 = x1[k0];
            float a3 = x1[k0 + 4];
            // exact-fp32 b.x partials (quad covers all 8 k's of this k-tile)
            float b0v = bs[k0];
            float b1v = bs[k0 + 4];
            bd0 += a0 * b0v + a2 * b1v;
            bd1 += a1 * b0v + a3 * b1v;
            uint32_t A0, A1, A2, A3;
            asm("cvt.rna.tf32.f32 %0, %1;" : "=r"(A0) : "f"(a0));
            asm("cvt.rna.tf32.f32 %0, %1;" : "=r"(A1) : "f"(a1));
            asm("cvt.rna.tf32.f32 %0, %1;" : "=r"(A2) : "f"(a2));
            asm("cvt.rna.tf32.f32 %0, %1;" : "=r"(A3) : "f"(a3));
            const int bc0 = k0 ^ qs;
            const int bc1 = (k0 + 4) ^ qs;
#pragma unroll
            for (int nt = 0; nt < 16; nt++) {
                // B fragment (col-major k8n8): b0=B[a][q+8nt], b1=B[a+4][q+8nt]
                const int brow = (nt * 8 + q) * 128;
                uint32_t B0 = __float_as_uint(Bs[brow + bc0]);
                uint32_t B1 = __float_as_uint(Bs[brow + bc1]);
                asm volatile(
                    "mma.sync.aligned.m16n8k8.row.col.f32.tf32.tf32.f32 "
                    "{%0,%1,%2,%3}, {%4,%5,%6,%7}, {%8,%9}, {%0,%1,%2,%3};"
                    : "+f"(acc[nt][0]), "+f"(acc[nt][1]),
                      "+f"(acc[nt][2]), "+f"(acc[nt][3])
                    : "r"(A0), "r"(A1), "r"(A2), "r"(A3), "r"(B0), "r"(B1));
            }
        }

        // y = sum_n z^2 + b.x, reduced across the 4-lane quad (lanes differ in bits 0-1).
        float t0 = bd0, t1 = bd1;
#pragma unroll
        for (int nt = 0; nt < 16; nt++) {
            t0 += acc[nt][0] * acc[nt][0] + acc[nt][1] * acc[nt][1];
            t1 += acc[nt][2] * acc[nt][2] + acc[nt][3] * acc[nt][3];
        }
        t0 += __shfl_xor_sync(0xffffffffu, t0, 1);
        t0 += __shfl_xor_sync(0xffffffffu, t0, 2);
        t1 += __shfl_xor_sync(0xffffffffu, t1, 1);
        t1 += __shfl_xor_sync(0xffffffffu, t1, 2);
        if (a == 0) {
            out[row0] = t0 + cval;          // row q of m-tile
            out[row0 + 8] = t1 + cval;      // row q+8
        }
    }
}

extern "C" void kernel_launch(void* const* d_in, const int* in_sizes, int n_in,
                              void* d_out, int out_size) {
    const float* x = (const float*)d_in[0];
    const float* L = (const float*)d_in[1];
    const float* b = (const float*)d_in[2];
    const float* c = (const float*)d_in[3];
    float* out = (float*)d_out;

    const int ntiles = out_size / 128;   // 4096 tiles of 128 rows
    const int smem_bytes = (128 * 128 + 128) * (int)sizeof(float);  // 66048

    cudaFuncSetAttribute(psd_quad_tf32_kernel,
                         cudaFuncAttributeMaxDynamicSharedMemorySize, smem_bytes);

    // Persistent grid: 2 CTAs per SM on 148-SM B200.
    psd_quad_tf32_kernel<<<296, 256, smem_bytes>>>(x, L, b, c, out, ntiles);
}

// round 4
// speedup vs baseline: 1.3023x; 1.3023x over previous
#include <cuda_runtime.h>
#include <cstdint>

// y_i = ||x_i tril(L)||^2 + b.x_i + c
// TF32 m16n8k8 mma; triangular block skip (136/256 mmas); x staged via cp.async
// into swizzled smem; warp computes m32 so each B fragment feeds 2 mmas.
// Persistent grid, packed-triangular B built once per CTA.

static __device__ __forceinline__ uint32_t f2tf32(float f) {
    uint32_t r; asm("cvt.rna.tf32.f32 %0, %1;" : "=r"(r) : "f"(f)); return r;
}

#define MMA_TF32(ACC, A0, A1, A2, A3, B0, B1)                                   \
    asm volatile("mma.sync.aligned.m16n8k8.row.col.f32.tf32.tf32.f32 "          \
                 "{%0,%1,%2,%3}, {%4,%5,%6,%7}, {%8,%9}, {%0,%1,%2,%3};"        \
                 : "+f"(ACC[0]), "+f"(ACC[1]), "+f"(ACC[2]), "+f"(ACC[3])       \
                 : "r"(A0), "r"(A1), "r"(A2), "r"(A3), "r"(B0), "r"(B1))

// smem word layout: Bp[136*64] | xs[128*128] | bsv[128]
#define BP_WORDS  (136 * 64)
#define XS_WORDS  (128 * 128)
#define SMEM_WORDS (BP_WORDS + XS_WORDS + 128)

__global__ __launch_bounds__(128, 2)
void psd_quad_kernel(const float* __restrict__ x,
                     const float* __restrict__ Lm,
                     const float* __restrict__ bv,
                     const float* __restrict__ cv,
                     float* __restrict__ out,
                     int ntiles)
{
    extern __shared__ float smem[];
    float* Bp  = smem;                       // packed triangular B, tf32
    float* xs  = smem + BP_WORDS;            // staged x tile (fp32, swizzled)
    float* bsv = smem + BP_WORDS + XS_WORDS; // b vector

    const int tid = threadIdx.x;

    // ---- one-time: build packed triangular B (B[n][k] = tril(L)[k][n]) ----
    // block blk=(kt,nt), nt<=kt; element (q,pc): logical kcol = pc ^ (q&4)
    // (conflict-free fragment reads), value = L[k][n], k=8kt+kcol, n=8nt+q.
    for (int idx = tid; idx < BP_WORDS; idx += 128) {
        int blk = idx >> 6, e = idx & 63;
        int kt = 0;
        while ((((kt + 1) * (kt + 2)) >> 1) <= blk) kt++;
        int nt = blk - ((kt * (kt + 1)) >> 1);
        int q = e >> 3, pc = e & 7;
        int kcol = pc ^ (q & 4);
        int k = 8 * kt + kcol, n = 8 * nt + q;
        float v = (k >= n) ? Lm[k * 128 + n] : 0.0f;
        Bp[idx] = __uint_as_float(f2tf32(v));
    }
    bsv[tid] = bv[tid];                      // blockDim == 128
    const float cval = cv[0];

    const int warp = tid >> 5, lane = tid & 31;
    const int q = lane >> 2, a = lane & 3;
    const int rowbase = warp * 32;           // warp owns 32 rows (two m16 tiles)
    const int q4 = q * 4;
    const int c0b = a ^ (q & 4);             // B phys col for kcol=a
    const uint32_t xs_b = (uint32_t)__cvta_generic_to_shared(xs);

    for (int tile = blockIdx.x; tile < ntiles; tile += gridDim.x) {
        __syncthreads();  // xs free (also orders Bp/bsv build on first iter)

        // ---- stage x tile: 128 rows x 32 chunks(16B), swizzled dst ----
        const float4* xt = (const float4*)(x + (size_t)tile * (128 * 128));
#pragma unroll
        for (int i = 0; i < 32; i++) {
            int idx = tid + i * 128;         // 0..4095
            int row = idx >> 5, ch = idx & 31;
            uint32_t dst = xs_b + (uint32_t)(row * 32 + (ch ^ (row & 7))) * 16u;
            asm volatile("cp.async.ca.shared.global [%0], [%1], 16;"
                         :: "r"(dst), "l"(xt + idx));
        }
        asm volatile("cp.async.commit_group;");
        asm volatile("cp.async.wait_group 0;");
        __syncthreads();

        float acc0[16][4], acc1[16][4];
#pragma unroll
        for (int nt = 0; nt < 16; nt++) {
#pragma unroll
            for (int j = 0; j < 4; j++) { acc0[nt][j] = 0.f; acc1[nt][j] = 0.f; }
        }
        float bd0 = 0.f, bd1 = 0.f, bd2 = 0.f, bd3 = 0.f;

        const float* xr0 = xs + (rowbase + q) * 128;  // row&7 == q for all four
        const float* xr1 = xr0 + 8 * 128;
        const float* xr2 = xr0 + 16 * 128;
        const float* xr3 = xr0 + 24 * 128;

#pragma unroll
        for (int kt = 0; kt < 16; kt++) {
            const int k0 = 8 * kt + a;
            const int col0 = k0 ^ q4, col1 = (k0 + 4) ^ q4;
            float a00 = xr0[col0], a02 = xr0[col1];
            float a01 = xr1[col0], a03 = xr1[col1];
            float a10 = xr2[col0], a12 = xr2[col1];
            float a11 = xr3[col0], a13 = xr3[col1];
            float b0v = bsv[k0], b1v = bsv[k0 + 4];
            bd0 += a00 * b0v + a02 * b1v;
            bd1 += a01 * b0v + a03 * b1v;
            bd2 += a10 * b0v + a12 * b1v;
            bd3 += a11 * b0v + a13 * b1v;
            uint32_t A00 = f2tf32(a00), A01 = f2tf32(a01);
            uint32_t A02 = f2tf32(a02), A03 = f2tf32(a03);
            uint32_t A10 = f2tf32(a10), A11 = f2tf32(a11);
            uint32_t A12 = f2tf32(a12), A13 = f2tf32(a13);
#pragma unroll
            for (int nt = 0; nt < 16; nt++) {
                if (nt > kt) continue;       // tril: B block is zero
                const int blk = ((kt * (kt + 1)) >> 1) + nt;
                const float* bb = Bp + blk * 64 + q * 8;
                uint32_t B0 = __float_as_uint(bb[c0b]);
                uint32_t B1 = __float_as_uint(bb[c0b ^ 4]);
                MMA_TF32(acc0[nt], A00, A01, A02, A03, B0, B1);  // rows q, q+8
                MMA_TF32(acc1[nt], A10, A11, A12, A13, B0, B1);  // rows q+16, q+24
            }
        }

        // ---- y = sum_n z^2 + b.x (+c); quad reduce over lanes a=0..3 ----
        float t0 = bd0, t1 = bd1, t2 = bd2, t3 = bd3;
#pragma unroll
        for (int nt = 0; nt < 16; nt++) {
            t0 += acc0[nt][0] * acc0[nt][0] + acc0[nt][1] * acc0[nt][1];
            t1 += acc0[nt][2] * acc0[nt][2] + acc0[nt][3] * acc0[nt][3];
            t2 += acc1[nt][0] * acc1[nt][0] + acc1[nt][1] * acc1[nt][1];
            t3 += acc1[nt][2] * acc1[nt][2] + acc1[nt][3] * acc1[nt][3];
        }
        t0 += __shfl_xor_sync(~0u, t0, 1); t0 += __shfl_xor_sync(~0u, t0, 2);
        t1 += __shfl_xor_sync(~0u, t1, 1); t1 += __shfl_xor_sync(~0u, t1, 2);
        t2 += __shfl_xor_sync(~0u, t2, 1); t2 += __shfl_xor_sync(~0u, t2, 2);
        t3 += __shfl_xor_sync(~0u, t3, 1); t3 += __shfl_xor_sync(~0u, t3, 2);
        if (a == 0) {
            float* o = out + (size_t)tile * 128 + rowbase + q;
            o[0]  = t0 + cval;
            o[8]  = t1 + cval;
            o[16] = t2 + cval;
            o[24] = t3 + cval;
        }
    }
}

extern "C" void kernel_launch(void* const* d_in, const int* in_sizes, int n_in,
                              void* d_out, int out_size) {
    const float* x = (const float*)d_in[0];
    const float* L = (const float*)d_in[1];
    const float* b = (const float*)d_in[2];
    const float* c = (const float*)d_in[3];
    float* out = (float*)d_out;

    const int ntiles = out_size / 128;                    // 4096
    const int smem_bytes = SMEM_WORDS * (int)sizeof(float); // ~100.9 KB

    cudaFuncSetAttribute(psd_quad_kernel,
                         cudaFuncAttributeMaxDynamicSharedMemorySize, smem_bytes);

    // 2 CTAs/SM on 148-SM B200: load/compute phases stagger across CTAs.
    psd_quad_kernel<<<296, 128, smem_bytes>>>(x, L, b, c, out, ntiles);
}

// round 5
// speedup vs baseline: 1.4952x; 1.1481x over previous
#include <cuda_runtime.h>
#include <cstdint>

// y_i = ||x_i tril(L)||^2 + b.x_i + c
// TF32 m16n8k8 mma; triangular block skip (136/256 mmas); x double-buffered via
// cp.async (prefetch tile t+grid while computing tile t); warp computes m32 so
// each B fragment feeds 2 mmas. Persistent grid, 1 CTA/SM.

static __device__ __forceinline__ uint32_t f2tf32(float f) {
    uint32_t r; asm("cvt.rna.tf32.f32 %0, %1;" : "=r"(r) : "f"(f)); return r;
}

#define MMA_TF32(ACC, A0, A1, A2, A3, B0, B1)                                   \
    asm volatile("mma.sync.aligned.m16n8k8.row.col.f32.tf32.tf32.f32 "          \
                 "{%0,%1,%2,%3}, {%4,%5,%6,%7}, {%8,%9}, {%0,%1,%2,%3};"        \
                 : "+f"(ACC[0]), "+f"(ACC[1]), "+f"(ACC[2]), "+f"(ACC[3])       \
                 : "r"(A0), "r"(A1), "r"(A2), "r"(A3), "r"(B0), "r"(B1))

// smem words: Bp[136*64] | xs[2][128*128] | bsv[128]
#define BP_WORDS   (136 * 64)
#define XS_WORDS   (128 * 128)
#define SMEM_WORDS (BP_WORDS + 2 * XS_WORDS + 128)

__global__ __launch_bounds__(128, 1)
void psd_quad_kernel(const float* __restrict__ x,
                     const float* __restrict__ Lm,
                     const float* __restrict__ bv,
                     const float* __restrict__ cv,
                     float* __restrict__ out,
                     int ntiles)
{
    extern __shared__ float smem[];
    float* Bp  = smem;                           // packed triangular B, tf32
    float* xs  = smem + BP_WORDS;                // 2 stages of x tile
    float* bsv = smem + BP_WORDS + 2 * XS_WORDS; // b vector

    const int tid = threadIdx.x;

    // ---- one-time: packed triangular B (B[n][k] = tril(L)[k][n]) ----
    // block blk=(kt,nt) nt<=kt; element (q,pc): kcol = pc ^ (q&4).
    for (int idx = tid; idx < BP_WORDS; idx += 128) {
        int blk = idx >> 6, e = idx & 63;
        int kt = 0;
        while ((((kt + 1) * (kt + 2)) >> 1) <= blk) kt++;
        int nt = blk - ((kt * (kt + 1)) >> 1);
        int q = e >> 3, pc = e & 7;
        int kcol = pc ^ (q & 4);
        int k = 8 * kt + kcol, n = 8 * nt + q;
        float v = (k >= n) ? Lm[k * 128 + n] : 0.0f;
        Bp[idx] = __uint_as_float(f2tf32(v));
    }
    bsv[tid] = bv[tid];
    const float cval = cv[0];

    const int warp = tid >> 5, lane = tid & 31;
    const int q = lane >> 2, a = lane & 3;
    const int rowbase = warp * 32;               // warp owns 32 rows
    const int q4 = q << 2;
    const int c0b = a ^ (q & 4);
    const uint32_t xs_b = (uint32_t)__cvta_generic_to_shared(xs);

    // precomputed per-thread swizzled stage offsets (bytes)
    uint32_t stoff[32];
#pragma unroll
    for (int i = 0; i < 32; i++) {
        int idx = tid + i * 128;
        int row = idx >> 5, ch = idx & 31;
        stoff[i] = (uint32_t)(row * 32 + (ch ^ (row & 7))) * 16u;
    }

    const int grid = gridDim.x;

    // ---- prologue: stage first tile into buffer 0 ----
    {
        const float4* xt = (const float4*)(x + (size_t)blockIdx.x * (128 * 128));
#pragma unroll
        for (int i = 0; i < 32; i++)
            asm volatile("cp.async.cg.shared.global [%0], [%1], 16;"
                         :: "r"(xs_b + stoff[i]), "l"(xt + tid + i * 128));
        asm volatile("cp.async.commit_group;");
    }

    int p = 0;
    for (int tile = blockIdx.x; tile < ntiles; tile += grid) {
        // ---- prefetch next tile into other buffer ----
        const int tn = tile + grid;
        if (tn < ntiles) {
            const uint32_t dstb = xs_b + (uint32_t)(p ^ 1) * (XS_WORDS * 4);
            const float4* xt = (const float4*)(x + (size_t)tn * (128 * 128));
#pragma unroll
            for (int i = 0; i < 32; i++)
                asm volatile("cp.async.cg.shared.global [%0], [%1], 16;"
                             :: "r"(dstb + stoff[i]), "l"(xt + tid + i * 128));
        }
        asm volatile("cp.async.commit_group;");   // commit (possibly empty) group
        asm volatile("cp.async.wait_group 1;");   // current buffer ready
        __syncthreads();

        const float* xb = xs + p * XS_WORDS;

        float acc0[16][4], acc1[16][4];
#pragma unroll
        for (int nt = 0; nt < 16; nt++) {
#pragma unroll
            for (int j = 0; j < 4; j++) { acc0[nt][j] = 0.f; acc1[nt][j] = 0.f; }
        }
        float bd0 = 0.f, bd1 = 0.f, bd2 = 0.f, bd3 = 0.f;

        const float* xr0 = xb + (rowbase + q) * 128;
        const float* xr1 = xr0 + 8 * 128;
        const float* xr2 = xr0 + 16 * 128;
        const float* xr3 = xr0 + 24 * 128;

#pragma unroll
        for (int kt = 0; kt < 16; kt++) {
            const int k0 = 8 * kt + a;
            const int col0 = k0 ^ q4, col1 = (k0 + 4) ^ q4;
            float a00 = xr0[col0], a02 = xr0[col1];
            float a01 = xr1[col0], a03 = xr1[col1];
            float a10 = xr2[col0], a12 = xr2[col1];
            float a11 = xr3[col0], a13 = xr3[col1];
            float b0v = bsv[k0], b1v = bsv[k0 + 4];
            bd0 += a00 * b0v + a02 * b1v;
            bd1 += a01 * b0v + a03 * b1v;
            bd2 += a10 * b0v + a12 * b1v;
            bd3 += a11 * b0v + a13 * b1v;
            uint32_t A00 = f2tf32(a00), A01 = f2tf32(a01);
            uint32_t A02 = f2tf32(a02), A03 = f2tf32(a03);
            uint32_t A10 = f2tf32(a10), A11 = f2tf32(a11);
            uint32_t A12 = f2tf32(a12), A13 = f2tf32(a13);
#pragma unroll
            for (int nt = 0; nt < 16; nt++) {
                if (nt > kt) continue;           // tril: block is zero
                const int blk = ((kt * (kt + 1)) >> 1) + nt;
                const float* bb = Bp + blk * 64 + q * 8;
                uint32_t B0 = __float_as_uint(bb[c0b]);
                uint32_t B1 = __float_as_uint(bb[c0b ^ 4]);
                MMA_TF32(acc0[nt], A00, A01, A02, A03, B0, B1);
                MMA_TF32(acc1[nt], A10, A11, A12, A13, B0, B1);
            }
        }

        // ---- y = sum_n z^2 + b.x (+c); quad reduce over a ----
        float t0 = bd0, t1 = bd1, t2 = bd2, t3 = bd3;
#pragma unroll
        for (int nt = 0; nt < 16; nt++) {
            t0 += acc0[nt][0] * acc0[nt][0] + acc0[nt][1] * acc0[nt][1];
            t1 += acc0[nt][2] * acc0[nt][2] + acc0[nt][3] * acc0[nt][3];
            t2 += acc1[nt][0] * acc1[nt][0] + acc1[nt][1] * acc1[nt][1];
            t3 += acc1[nt][2] * acc1[nt][2] + acc1[nt][3] * acc1[nt][3];
        }
        t0 += __shfl_xor_sync(~0u, t0, 1); t0 += __shfl_xor_sync(~0u, t0, 2);
        t1 += __shfl_xor_sync(~0u, t1, 1); t1 += __shfl_xor_sync(~0u, t1, 2);
        t2 += __shfl_xor_sync(~0u, t2, 1); t2 += __shfl_xor_sync(~0u, t2, 2);
        t3 += __shfl_xor_sync(~0u, t3, 1); t3 += __shfl_xor_sync(~0u, t3, 2);
        if (a == 0) {
            float* o = out + (size_t)tile * 128 + rowbase + q;
            o[0]  = t0 + cval;
            o[8]  = t1 + cval;
            o[16] = t2 + cval;
            o[24] = t3 + cval;
        }
        __syncthreads();   // all reads of buffer p done before it is overwritten
        p ^= 1;
    }
}

extern "C" void kernel_launch(void* const* d_in, const int* in_sizes, int n_in,
                              void* d_out, int out_size) {
    const float* x = (const float*)d_in[0];
    const float* L = (const float*)d_in[1];
    const float* b = (const float*)d_in[2];
    const float* c = (const float*)d_in[3];
    float* out = (float*)d_out;

    const int ntiles = out_size / 128;                      // 4096
    const int smem_bytes = SMEM_WORDS * (int)sizeof(float); // ~163.5 KB

    cudaFuncSetAttribute(psd_quad_kernel,
                         cudaFuncAttributeMaxDynamicSharedMemorySize, smem_bytes);

    // 1 CTA/SM persistent grid; overlap enforced by double buffering.
    psd_quad_kernel<<<148, 128, smem_bytes>>>(x, L, b, c, out, ntiles);
}

// round 6
// speedup vs baseline: 1.8144x; 1.2135x over previous
#include <cuda_runtime.h>
#include <cstdint>

// y_i = ||x_i tril(L)||^2 + b.x_i + c
// TF32 m16n8k8 mma; triangular block skip (136/256 mmas); x double-buffered via
// cp.async; 8 warps/CTA, each warp owns one m16 tile (2 warps/SMSP for latency
// hiding). Persistent grid, 1 CTA/SM.

static __device__ __forceinline__ uint32_t f2tf32(float f) {
    uint32_t r; asm("cvt.rna.tf32.f32 %0, %1;" : "=r"(r) : "f"(f)); return r;
}

#define MMA_TF32(ACC, A0, A1, A2, A3, B0, B1)                                   \
    asm volatile("mma.sync.aligned.m16n8k8.row.col.f32.tf32.tf32.f32 "          \
                 "{%0,%1,%2,%3}, {%4,%5,%6,%7}, {%8,%9}, {%0,%1,%2,%3};"        \
                 : "+f"(ACC[0]), "+f"(ACC[1]), "+f"(ACC[2]), "+f"(ACC[3])       \
                 : "r"(A0), "r"(A1), "r"(A2), "r"(A3), "r"(B0), "r"(B1))

// smem words: Bp[136*64] | xs[2][128*128] | bsv[128]
#define BP_WORDS   (136 * 64)
#define XS_WORDS   (128 * 128)
#define SMEM_WORDS (BP_WORDS + 2 * XS_WORDS + 128)

__global__ __launch_bounds__(256, 1)
void psd_quad_kernel(const float* __restrict__ x,
                     const float* __restrict__ Lm,
                     const float* __restrict__ bv,
                     const float* __restrict__ cv,
                     float* __restrict__ out,
                     int ntiles)
{
    extern __shared__ float smem[];
    float* Bp  = smem;                           // packed triangular B, tf32
    float* xs  = smem + BP_WORDS;                // 2 stages of x tile
    float* bsv = smem + BP_WORDS + 2 * XS_WORDS; // b vector

    const int tid = threadIdx.x;

    // ---- one-time: packed triangular B (B[n][k] = tril(L)[k][n]) ----
    // block blk=(kt,nt) nt<=kt; element (q,pc): kcol = pc ^ (q&4).
    for (int idx = tid; idx < BP_WORDS; idx += 256) {
        int blk = idx >> 6, e = idx & 63;
        int kt = 0;
        while ((((kt + 1) * (kt + 2)) >> 1) <= blk) kt++;
        int nt = blk - ((kt * (kt + 1)) >> 1);
        int q = e >> 3, pc = e & 7;
        int kcol = pc ^ (q & 4);
        int k = 8 * kt + kcol, n = 8 * nt + q;
        float v = (k >= n) ? Lm[k * 128 + n] : 0.0f;
        Bp[idx] = __uint_as_float(f2tf32(v));
    }
    if (tid < 128) bsv[tid] = bv[tid];
    const float cval = cv[0];

    const int warp = tid >> 5, lane = tid & 31;
    const int q = lane >> 2, a = lane & 3;
    const int rowbase = warp * 16;               // warp owns 16 rows (one m16)
    const int q4 = q << 2;
    const int c0b = a ^ (q & 4);
    const uint32_t xs_b = (uint32_t)__cvta_generic_to_shared(xs);

    // precomputed per-thread swizzled stage offsets (bytes): 4096 chunks / 256 thr
    uint32_t stoff[16];
#pragma unroll
    for (int i = 0; i < 16; i++) {
        int idx = tid + i * 256;
        int row = idx >> 5, ch = idx & 31;
        stoff[i] = (uint32_t)(row * 32 + (ch ^ (row & 7))) * 16u;
    }

    const int grid = gridDim.x;

    // ---- prologue: stage first tile into buffer 0 ----
    {
        const float4* xt = (const float4*)(x + (size_t)blockIdx.x * (128 * 128));
#pragma unroll
        for (int i = 0; i < 16; i++)
            asm volatile("cp.async.cg.shared.global [%0], [%1], 16;"
                         :: "r"(xs_b + stoff[i]), "l"(xt + tid + i * 256));
        asm volatile("cp.async.commit_group;");
    }

    int p = 0;
    for (int tile = blockIdx.x; tile < ntiles; tile += grid) {
        // ---- prefetch next tile into the other buffer ----
        const int tn = tile + grid;
        if (tn < ntiles) {
            const uint32_t dstb = xs_b + (uint32_t)(p ^ 1) * (XS_WORDS * 4);
            const float4* xt = (const float4*)(x + (size_t)tn * (128 * 128));
#pragma unroll
            for (int i = 0; i < 16; i++)
                asm volatile("cp.async.cg.shared.global [%0], [%1], 16;"
                             :: "r"(dstb + stoff[i]), "l"(xt + tid + i * 256));
        }
        asm volatile("cp.async.commit_group;");   // commit (possibly empty) group
        asm volatile("cp.async.wait_group 1;");   // current buffer ready
        __syncthreads();

        const float* xb = xs + p * XS_WORDS;

        float acc[16][4];
#pragma unroll
        for (int nt = 0; nt < 16; nt++) {
#pragma unroll
            for (int j = 0; j < 4; j++) acc[nt][j] = 0.f;
        }
        float bd0 = 0.f, bd1 = 0.f;

        const float* xr0 = xb + (rowbase + q) * 128;
        const float* xr1 = xr0 + 8 * 128;

#pragma unroll
        for (int kt = 0; kt < 16; kt++) {
            const int k0 = 8 * kt + a;
            const int col0 = k0 ^ q4, col1 = (k0 + 4) ^ q4;
            float a0 = xr0[col0], a2 = xr0[col1];
            float a1 = xr1[col0], a3 = xr1[col1];
            float b0v = bsv[k0], b1v = bsv[k0 + 4];
            bd0 += a0 * b0v + a2 * b1v;
            bd1 += a1 * b0v + a3 * b1v;
            uint32_t A0 = f2tf32(a0), A1 = f2tf32(a1);
            uint32_t A2 = f2tf32(a2), A3 = f2tf32(a3);
#pragma unroll
            for (int nt = 0; nt < 16; nt++) {
                if (nt > kt) continue;           // tril: block is zero
                const int blk = ((kt * (kt + 1)) >> 1) + nt;
                const float* bb = Bp + blk * 64 + q * 8;
                uint32_t B0 = __float_as_uint(bb[c0b]);
                uint32_t B1 = __float_as_uint(bb[c0b ^ 4]);
                MMA_TF32(acc[nt], A0, A1, A2, A3, B0, B1);
            }
        }

        // ---- y = sum_n z^2 + b.x (+c); quad reduce over a ----
        float t0 = bd0, t1 = bd1;
#pragma unroll
        for (int nt = 0; nt < 16; nt++) {
            t0 += acc[nt][0] * acc[nt][0] + acc[nt][1] * acc[nt][1];
            t1 += acc[nt][2] * acc[nt][2] + acc[nt][3] * acc[nt][3];
        }
        t0 += __shfl_xor_sync(~0u, t0, 1); t0 += __shfl_xor_sync(~0u, t0, 2);
        t1 += __shfl_xor_sync(~0u, t1, 1); t1 += __shfl_xor_sync(~0u, t1, 2);
        if (a == 0) {
            float* o = out + (size_t)tile * 128 + rowbase + q;
            o[0] = t0 + cval;
            o[8] = t1 + cval;
        }
        __syncthreads();   // all reads of buffer p done before it is overwritten
        p ^= 1;
    }
}

extern "C" void kernel_launch(void* const* d_in, const int* in_sizes, int n_in,
                              void* d_out, int out_size) {
    const float* x = (const float*)d_in[0];
    const float* L = (const float*)d_in[1];
    const float* b = (const float*)d_in[2];
    const float* c = (const float*)d_in[3];
    float* out = (float*)d_out;

    const int ntiles = out_size / 128;                      // 4096
    const int smem_bytes = SMEM_WORDS * (int)sizeof(float); // ~163.5 KB

    cudaFuncSetAttribute(psd_quad_kernel,
                         cudaFuncAttributeMaxDynamicSharedMemorySize, smem_bytes);

    // 1 CTA/SM persistent grid; 8 warps = 2/SMSP for latency hiding.
    psd_quad_kernel<<<148, 256, smem_bytes>>>(x, L, b, c, out, ntiles);
}